// round 6
// baseline (speedup 1.0000x reference)
#include <cuda_runtime.h>
#include <cuda_bf16.h>

// MolecularGraphNeuralNetwork — fused kernel, v5b: 2 molecules per CTA.
//
// 128 CTAs x 128 threads (4 warps). Warp g owns atoms 8g..8g+7 of BOTH
// molecules 2*bid and 2*bid+1. One weight load feeds 16 atom-accumulators
// (8 per molecule): halves the dominant redundant W LDS stream and doubles
// per-warp ILP (32 independent f32x2 chains). One CTA per SM -> no 2-CTA
// straggler SMs, no phase-aligned cross-CTA LDS contention.
//
// v5b: shared state moved to DYNAMIC shared memory (62 KB > the 48 KB
// static-declaration limit; well under the 227 KB carveout).

#define T_ATOMS 8192
#define B_MOL   256
#define APM     32
#define DIM     64
#define LH      3
#define WPAD    68   // 68 = 4 (mod 32): conflict-free strided LDS.128 on W rows
#define HPAD    36   // 36 = 4 (mod 32): conflict-free strided LDS/STS.128 on hT rows

struct SmemLayout {
    float vP[2][APM][DIM];     // per-mol atom features
    float hT[2][DIM][HPAD];    // hT[s][d][j] = h[j][d]
    float As[2][APM][APM];     // per-mol diagonal adjacency blocks
    float WsP[DIM][WPAD];      // current layer weight [d][k] (shared by both mols)
    float molP[2][4][DIM];     // per-mol, per-warp partial sums
    float molA[2][DIM];
    float molB[2][DIM];
};

__device__ __forceinline__ void ffma2(unsigned long long& c,
                                      unsigned long long a,
                                      unsigned long long b) {
    asm("fma.rn.f32x2 %0, %1, %2, %0;" : "+l"(c) : "l"(a), "l"(b));
}
__device__ __forceinline__ float hsum2(unsigned long long x) {
    return __uint_as_float((unsigned)x) + __uint_as_float((unsigned)(x >> 32));
}
__device__ __forceinline__ unsigned long long pack2(float lo, float hi) {
    return (unsigned long long)__float_as_uint(lo) |
           ((unsigned long long)__float_as_uint(hi) << 32);
}

__global__ __launch_bounds__(128)
void gnn_mol_kernel(const int*   __restrict__ fp,
                    const float* __restrict__ adj,
                    const float* __restrict__ embed,
                    const float* __restrict__ W_fp,
                    const float* __restrict__ b_fp,
                    const float* __restrict__ W_out,
                    const float* __restrict__ b_out,
                    const float* __restrict__ W_prop,
                    const float* __restrict__ b_prop,
                    float*       __restrict__ out)
{
    extern __shared__ char smem_raw[];
    SmemLayout& S = *reinterpret_cast<SmemLayout*>(smem_raw);

    const int bid  = blockIdx.x;          // handles molecules 2*bid, 2*bid+1
    const int tid  = threadIdx.x;
    const int lane = tid & 31;
    const int g    = tid >> 5;
    const int i0   = g * 8;

    // ---- init loads -------------------------------------------------------
    float bia[LH], bib[LH];
    #pragma unroll
    for (int l = 0; l < LH; l++) {
        bia[l] = b_fp[l * DIM + lane];
        bib[l] = b_fp[l * DIM + lane + 32];
    }
    // adjacency blocks: 2 x 1024 floats = 512 float4, 4 per thread, coalesced
    #pragma unroll
    for (int t = 0; t < 4; t++) {
        int e = tid + t * 128;            // float4 slot
        int s = e >> 8, r = e & 255;
        int i = r >> 3, c = r & 7;
        int mm = 2 * bid + s;
        const float4 a4 = *reinterpret_cast<const float4*>(
            &adj[(size_t)(mm * APM + i) * T_ATOMS + (size_t)mm * APM + 4 * c]);
        *reinterpret_cast<float4*>(&S.As[s][i][4 * c]) = a4;
    }
    // layer-0 weights: LDG.128 -> STS.128
    {
        const float4* W4 = reinterpret_cast<const float4*>(W_fp);
        #pragma unroll
        for (int t = 0; t < 8; t++) {
            int e = tid + t * 128;
            int d = e >> 4, c = e & 15;
            *reinterpret_cast<float4*>(&S.WsP[d][4 * c]) = W4[e];
        }
    }
    // embedding gather: this warp's 8 atoms of each molecule
    #pragma unroll
    for (int s = 0; s < 2; s++) {
        #pragma unroll
        for (int q = 0; q < 8; q++) {
            int f = fp[(2 * bid + s) * APM + i0 + q];
            S.vP[s][i0 + q][lane]      = embed[(size_t)f * DIM + lane];
            S.vP[s][i0 + q][lane + 32] = embed[(size_t)f * DIM + lane + 32];
        }
    }
    __syncthreads();

    // ---- 3 GNN layers ------------------------------------------------------
    for (int l = 0; l < LH; l++) {
        // MLP: h[i][d] = relu(b[d] + sum_k v[i][k] W[d][k]) for both molecules.
        // 32 independent packed accumulators per thread.
        unsigned long long acc[2][8][2];
        #pragma unroll
        for (int s = 0; s < 2; s++)
            #pragma unroll
            for (int q = 0; q < 8; q++) { acc[s][q][0] = 0ull; acc[s][q][1] = 0ull; }

        #pragma unroll 4
        for (int pc = 0; pc < DIM; pc += 4) {
            const ulonglong2 wa = *reinterpret_cast<const ulonglong2*>(&S.WsP[lane][pc]);
            const ulonglong2 wb = *reinterpret_cast<const ulonglong2*>(&S.WsP[lane + 32][pc]);
            #pragma unroll
            for (int s = 0; s < 2; s++) {
                #pragma unroll
                for (int q = 0; q < 8; q++) {
                    const ulonglong2 vv =
                        *reinterpret_cast<const ulonglong2*>(&S.vP[s][i0 + q][pc]);
                    ffma2(acc[s][q][0], vv.x, wa.x);
                    ffma2(acc[s][q][0], vv.y, wa.y);
                    ffma2(acc[s][q][1], vv.x, wb.x);
                    ffma2(acc[s][q][1], vv.y, wb.y);
                }
            }
        }

        float hs0[2][8], hs1[2][8];
        #pragma unroll
        for (int s = 0; s < 2; s++) {
            #pragma unroll
            for (int q = 0; q < 8; q++) {
                hs0[s][q] = fmaxf(hsum2(acc[s][q][0]) + bia[l], 0.0f);
                hs1[s][q] = fmaxf(hsum2(acc[s][q][1]) + bib[l], 0.0f);
            }
            // vectorized transpose store: stride 36 -> conflict-free STS.128
            *reinterpret_cast<float4*>(&S.hT[s][lane][i0]) =
                make_float4(hs0[s][0], hs0[s][1], hs0[s][2], hs0[s][3]);
            *reinterpret_cast<float4*>(&S.hT[s][lane][i0 + 4]) =
                make_float4(hs0[s][4], hs0[s][5], hs0[s][6], hs0[s][7]);
            *reinterpret_cast<float4*>(&S.hT[s][lane + 32][i0]) =
                make_float4(hs1[s][0], hs1[s][1], hs1[s][2], hs1[s][3]);
            *reinterpret_cast<float4*>(&S.hT[s][lane + 32][i0 + 4]) =
                make_float4(hs1[s][4], hs1[s][5], hs1[s][6], hs1[s][7]);
        }
        __syncthreads();   // hT complete; MLP reads of WsP done

        // prefetch next layer's weights (WsP unused until after next barrier)
        if (l + 1 < LH) {
            const float4* Wn4 =
                reinterpret_cast<const float4*>(W_fp + (l + 1) * DIM * DIM);
            #pragma unroll
            for (int t = 0; t < 8; t++) {
                int e = tid + t * 128;
                int d = e >> 4, c = e & 15;
                *reinterpret_cast<float4*>(&S.WsP[d][4 * c]) = Wn4[e];
            }
        }

        // propagation + norm, both molecules
        unsigned long long p[2][8][2];
        #pragma unroll
        for (int s = 0; s < 2; s++)
            #pragma unroll
            for (int q = 0; q < 8; q++) {
                p[s][q][0] = pack2(hs0[s][q], 0.0f);
                p[s][q][1] = pack2(hs1[s][q], 0.0f);
            }
        #pragma unroll 2
        for (int jc = 0; jc < APM; jc += 4) {
            #pragma unroll
            for (int s = 0; s < 2; s++) {
                const ulonglong2 h0 =
                    *reinterpret_cast<const ulonglong2*>(&S.hT[s][lane][jc]);
                const ulonglong2 h1 =
                    *reinterpret_cast<const ulonglong2*>(&S.hT[s][lane + 32][jc]);
                #pragma unroll
                for (int q = 0; q < 8; q++) {
                    const ulonglong2 a2 =
                        *reinterpret_cast<const ulonglong2*>(&S.As[s][i0 + q][jc]);
                    ffma2(p[s][q][0], a2.x, h0.x);
                    ffma2(p[s][q][0], a2.y, h0.y);
                    ffma2(p[s][q][1], a2.x, h1.x);
                    ffma2(p[s][q][1], a2.y, h1.y);
                }
            }
        }

        #pragma unroll
        for (int s = 0; s < 2; s++) {
            #pragma unroll
            for (int q = 0; q < 8; q++) {
                const float s0 = hsum2(p[s][q][0]);
                const float s1 = hsum2(p[s][q][1]);
                float ss = s0 * s0 + s1 * s1;
                #pragma unroll
                for (int o = 16; o; o >>= 1)
                    ss += __shfl_xor_sync(0xffffffffu, ss, o);
                const float inv = rsqrtf(fmaxf(ss, 1e-24f));  // 1/max(||.||,1e-12)
                S.vP[s][i0 + q][lane]      = s0 * inv;
                S.vP[s][i0 + q][lane + 32] = s1 * inv;
            }
        }
        __syncthreads();   // hT free; WsP prefetch published
    }

    // ---- molecular vectors -------------------------------------------------
    #pragma unroll
    for (int s = 0; s < 2; s++) {
        float sx = 0.0f, sy = 0.0f;
        #pragma unroll
        for (int q = 0; q < 8; q++) {
            sx += S.vP[s][i0 + q][lane];
            sy += S.vP[s][i0 + q][lane + 32];
        }
        S.molP[s][g][lane]      = sx;
        S.molP[s][g][lane + 32] = sy;
    }
    __syncthreads();

    // ---- output MLP: threads 0-63 -> mol 0, threads 64-127 -> mol 1 -------
    {
        const int s = tid >> 6;
        const int d = tid & 63;
        S.molA[s][d] = S.molP[s][0][d] + S.molP[s][1][d]
                     + S.molP[s][2][d] + S.molP[s][3][d];
    }
    __syncthreads();
    {
        const int s = tid >> 6;
        const int d = tid & 63;
        const float* Wr = W_out + d * DIM;
        float a = b_out[d];
        #pragma unroll
        for (int k = 0; k < DIM; k += 4) {
            const float4 w4 = *reinterpret_cast<const float4*>(&Wr[k]);
            a += S.molA[s][k] * w4.x + S.molA[s][k + 1] * w4.y
               + S.molA[s][k + 2] * w4.z + S.molA[s][k + 3] * w4.w;
        }
        S.molB[s][d] = fmaxf(a, 0.0f);
    }
    __syncthreads();
    {
        const int s = tid >> 6;
        const int d = tid & 63;
        const float* Wr = W_out + DIM * DIM + d * DIM;
        float a = b_out[DIM + d];
        #pragma unroll
        for (int k = 0; k < DIM; k += 4) {
            const float4 w4 = *reinterpret_cast<const float4*>(&Wr[k]);
            a += S.molB[s][k] * w4.x + S.molB[s][k + 1] * w4.y
               + S.molB[s][k + 2] * w4.z + S.molB[s][k + 3] * w4.w;
        }
        S.molA[s][d] = fmaxf(a, 0.0f);
    }
    __syncthreads();

    // ---- final property: warp 0 -> mol 0, warp 1 -> mol 1 ------------------
    if (g < 2) {
        float sum = S.molA[g][lane] * W_prop[lane]
                  + S.molA[g][lane + 32] * W_prop[lane + 32];
        #pragma unroll
        for (int o = 16; o; o >>= 1)
            sum += __shfl_xor_sync(0xffffffffu, sum, o);
        if (lane == 0) out[2 * bid + g] = sum + b_prop[0];
    }
}

extern "C" void kernel_launch(void* const* d_in, const int* in_sizes, int n_in,
                              void* d_out, int out_size)
{
    // metadata order: fingerprints, adjacency, segment_ids, embed,
    //                 W_fp, b_fp, W_out, b_out, W_prop, b_prop
    const int*   fp     = (const int*)  d_in[0];
    const float* adj    = (const float*)d_in[1];
    // d_in[2] = segment_ids: repeat(arange(256), 32), used implicitly
    const float* embed  = (const float*)d_in[3];
    const float* W_fp   = (const float*)d_in[4];
    const float* b_fp   = (const float*)d_in[5];
    const float* W_out  = (const float*)d_in[6];
    const float* b_out  = (const float*)d_in[7];
    const float* W_prop = (const float*)d_in[8];
    const float* b_prop = (const float*)d_in[9];
    float* outp = (float*)d_out;

    const int smem_bytes = (int)sizeof(SmemLayout);   // ~62 KB
    // Idempotent, immediate host-side call: no allocation, capture-safe.
    cudaFuncSetAttribute(gnn_mol_kernel,
                         cudaFuncAttributeMaxDynamicSharedMemorySize, smem_bytes);

    gnn_mol_kernel<<<B_MOL / 2, 128, smem_bytes>>>(fp, adj, embed, W_fp, b_fp,
                                                   W_out, b_out, W_prop, b_prop,
                                                   outp);
}